// round 1
// baseline (speedup 1.0000x reference)
#include <cuda_runtime.h>

// MMD loss: X,Y [4096,256] fp32 -> scalar fp32.
//   Z = [X;Y] (8192x256)
//   d2(i,j) = s_i + s_j - 2 z_i.z_j  (clamped at 0)
//   bw = sum(d2)/(N^2-N)  computed analytically: 2N*sum(s) - 2*||colsum||^2
//   K = sum_m exp(-d2/(bw*m)), m = {1/4,1/2,1,2,4}  via e1=2^(-d2*log2e/(4bw)) and squarings
//   out = (1/n^2) * sum_ij sigma_i sigma_j K(i,j),  sigma = +1 (X rows) / -1 (Y rows)

#define N_HALF 4096
#define N_TOT  8192
#define DIM    256
#define BM     128
#define BK     8
#define TILES  64            // N_TOT / BM
#define HALF_TILES 32        // N_HALF / BM

__device__ float  g_snorm[N_TOT];
__device__ double g_colpart[256 * 256];   // [block][col] partial column sums
__device__ float  g_coef;                 // log2(e) / (4*bw)
__device__ double g_part[TILES * TILES];  // per-tile signed partial sums

__device__ __forceinline__ const float* zptr(const float* X, const float* Y, int r) {
    return (r < N_HALF) ? (X + (size_t)r * DIM) : (Y + (size_t)(r - N_HALF) * DIM);
}

__device__ __forceinline__ float ex2f(float x) {
    float y;
    asm("ex2.approx.ftz.f32 %0, %1;" : "=f"(y) : "f"(x));
    return y;
}

// ---------------------------------------------------------------------------
// Kernel 1: squared row norms. grid=1024 blocks x 256 thr; warp w of block b
// handles row b*8 + w (coalesced across lanes).
// ---------------------------------------------------------------------------
__global__ void __launch_bounds__(256) k_norms(const float* __restrict__ X,
                                               const float* __restrict__ Y) {
    int warp = threadIdx.x >> 5, lane = threadIdx.x & 31;
    int row = blockIdx.x * 8 + warp;
    const float* zr = zptr(X, Y, row);
    float s = 0.f;
    #pragma unroll
    for (int c = lane; c < DIM; c += 32) {
        float v = zr[c];
        s = fmaf(v, v, s);
    }
    #pragma unroll
    for (int o = 16; o; o >>= 1) s += __shfl_xor_sync(0xffffffffu, s, o);
    if (lane == 0) g_snorm[row] = s;
}

// ---------------------------------------------------------------------------
// Kernel 2: partial column sums. grid=256 blocks x 256 thr; block b sums rows
// [b*32, b*32+32) into g_colpart[b][col]. Deterministic order.
// ---------------------------------------------------------------------------
__global__ void __launch_bounds__(256) k_colsum(const float* __restrict__ X,
                                                const float* __restrict__ Y) {
    int col = threadIdx.x;
    int r0 = blockIdx.x * 32;
    double acc = 0.0;
    #pragma unroll 4
    for (int r = 0; r < 32; r++)
        acc += (double)zptr(X, Y, r0 + r)[col];
    g_colpart[blockIdx.x * 256 + col] = acc;
}

// ---------------------------------------------------------------------------
// Kernel 3: bandwidth -> exponent coefficient. Single block, deterministic.
// ---------------------------------------------------------------------------
__global__ void __launch_bounds__(256) k_bw() {
    __shared__ double sh[256];
    int t = threadIdx.x;

    double ss = 0.0;
    for (int i = t; i < N_TOT; i += 256) ss += (double)g_snorm[i];
    sh[t] = ss;
    __syncthreads();
    for (int o = 128; o; o >>= 1) {
        if (t < o) sh[t] += sh[t + o];
        __syncthreads();
    }
    double sum_s = sh[0];
    __syncthreads();

    double C = 0.0;
    for (int b = 0; b < 256; b++) C += g_colpart[b * 256 + t];
    sh[t] = C * C;
    __syncthreads();
    for (int o = 128; o; o >>= 1) {
        if (t < o) sh[t] += sh[t + o];
        __syncthreads();
    }
    if (t == 0) {
        double total = 2.0 * (double)N_TOT * sum_s - 2.0 * sh[0];
        double bw = total / ((double)N_TOT * (double)N_TOT - (double)N_TOT);
        g_coef = (float)(1.4426950408889634 / (4.0 * bw));
    }
}

// ---------------------------------------------------------------------------
// Kernel 4: main pairwise tile kernel. grid (64,64); tiles with tj<ti exit
// (symmetry, weight 2 off-diagonal). 256 threads, 8x8 register tiles, BK=8.
// ---------------------------------------------------------------------------
__global__ void __launch_bounds__(256) k_main(const float* __restrict__ X,
                                              const float* __restrict__ Y) {
    int tj = blockIdx.x, ti = blockIdx.y;
    int bid = ti * TILES + tj;
    int tid = threadIdx.x;
    if (tj < ti) {                 // symmetric half: contribute 0 deterministically
        if (tid == 0) g_part[bid] = 0.0;
        return;
    }

    __shared__ float As[BK][BM];
    __shared__ float Bs[BK][BM];
    __shared__ double red[256];

    int tx = tid & 15, ty = tid >> 4;
    int lrow = tid >> 1;           // 0..127
    int lc4  = (tid & 1) << 2;     // 0 or 4
    const float* arow = zptr(X, Y, ti * BM + lrow) + lc4;
    const float* brow = zptr(X, Y, tj * BM + lrow) + lc4;

    float acc[8][8];
    #pragma unroll
    for (int u = 0; u < 8; u++)
        #pragma unroll
        for (int v = 0; v < 8; v++) acc[u][v] = 0.f;

    float4 ap = *(const float4*)(arow);
    float4 bp = *(const float4*)(brow);

    for (int k0 = 0; k0 < DIM; k0 += BK) {
        __syncthreads();
        As[lc4 + 0][lrow] = ap.x; As[lc4 + 1][lrow] = ap.y;
        As[lc4 + 2][lrow] = ap.z; As[lc4 + 3][lrow] = ap.w;
        Bs[lc4 + 0][lrow] = bp.x; Bs[lc4 + 1][lrow] = bp.y;
        Bs[lc4 + 2][lrow] = bp.z; Bs[lc4 + 3][lrow] = bp.w;
        __syncthreads();

        if (k0 + BK < DIM) {       // prefetch next slab into registers
            ap = *(const float4*)(arow + k0 + BK);
            bp = *(const float4*)(brow + k0 + BK);
        }

        #pragma unroll
        for (int k = 0; k < BK; k++) {
            float4 a0 = *(const float4*)&As[k][ty * 8];
            float4 a1 = *(const float4*)&As[k][ty * 8 + 4];
            float4 b0 = *(const float4*)&Bs[k][tx * 8];
            float4 b1 = *(const float4*)&Bs[k][tx * 8 + 4];
            float ra[8] = {a0.x, a0.y, a0.z, a0.w, a1.x, a1.y, a1.z, a1.w};
            float rb[8] = {b0.x, b0.y, b0.z, b0.w, b1.x, b1.y, b1.z, b1.w};
            #pragma unroll
            for (int u = 0; u < 8; u++)
                #pragma unroll
                for (int v = 0; v < 8; v++)
                    acc[u][v] = fmaf(ra[u], rb[v], acc[u][v]);
        }
    }

    // Epilogue: d2 -> 5-kernel sum via ex2 + squaring chain.
    int ib = ti * BM + ty * 8;
    int jb = tj * BM + tx * 8;
    float sA[8], sB[8];
    #pragma unroll
    for (int u = 0; u < 8; u++) sA[u] = g_snorm[ib + u];
    #pragma unroll
    for (int v = 0; v < 8; v++) sB[v] = g_snorm[jb + v];
    float c = g_coef;

    float psum = 0.f;
    #pragma unroll
    for (int u = 0; u < 8; u++) {
        #pragma unroll
        for (int v = 0; v < 8; v++) {
            float d2 = fmaf(-2.f, acc[u][v], sA[u] + sB[v]);
            d2 = fmaxf(d2, 0.f);
            float e  = ex2f(-d2 * c);   // exp(-d2/(4 bw))   mult 4
            float t2 = e * e;           // mult 2
            float ks = e + t2;
            float t4 = t2 * t2;  ks += t4;   // mult 1
            float t8 = t4 * t4;  ks += t8;   // mult 1/2
            ks += t8 * t8;                   // mult 1/4
            psum += ks;
        }
    }

    double w = ((ti < HALF_TILES) == (tj < HALF_TILES)) ? 1.0 : -1.0;
    if (ti != tj) w *= 2.0;                 // symmetric off-diagonal tile pair

    red[tid] = (double)psum * w;
    __syncthreads();
    for (int o = 128; o; o >>= 1) {
        if (tid < o) red[tid] += red[tid + o];
        __syncthreads();
    }
    if (tid == 0) g_part[bid] = red[0];
}

// ---------------------------------------------------------------------------
// Kernel 5: deterministic final reduction + scale.
// ---------------------------------------------------------------------------
__global__ void __launch_bounds__(256) k_final(float* __restrict__ out) {
    __shared__ double sh[256];
    int t = threadIdx.x;
    double a = 0.0;
    for (int i = t; i < TILES * TILES; i += 256) a += g_part[i];
    sh[t] = a;
    __syncthreads();
    for (int o = 128; o; o >>= 1) {
        if (t < o) sh[t] += sh[t + o];
        __syncthreads();
    }
    if (t == 0)
        out[0] = (float)(sh[0] / ((double)N_HALF * (double)N_HALF));
}

extern "C" void kernel_launch(void* const* d_in, const int* in_sizes, int n_in,
                              void* d_out, int out_size) {
    const float* X = (const float*)d_in[0];
    const float* Y = (const float*)d_in[1];
    float* out = (float*)d_out;
    (void)in_sizes; (void)n_in; (void)out_size;

    k_norms<<<1024, 256>>>(X, Y);
    k_colsum<<<256, 256>>>(X, Y);
    k_bw<<<1, 256>>>();
    dim3 grid(TILES, TILES);
    k_main<<<grid, 256>>>(X, Y);
    k_final<<<1, 256>>>(out);
}

// round 2
// speedup vs baseline: 1.2810x; 1.2810x over previous
#include <cuda_runtime.h>

// MMD loss: X,Y [4096,256] fp32 -> scalar fp32.
//   d2(i,j) = s_i + s_j - 2 z_i.z_j ; bw analytically from norms + column sums.
//   K = sum_m exp(-d2/(bw*m)), m = 2^{-2..2}, via one ex2 + squaring chain.
//   Triangular tile launch (2080 CTAs), FFMA2 (fp32x2) inner product,
//   conflict-free split fragments, double-buffered smem.

#define N_HALF 4096
#define N_TOT  8192
#define DIM    256
#define BM     128
#define BK     8
#define TILES  64
#define HALF_TILES 32
#define NPAIRS 2080          // TILES*(TILES+1)/2

__device__ float  g_snorm[N_TOT];
__device__ double g_colpart[256 * 256];
__device__ float  g_coef;                 // log2(e)/(4*bw)
__device__ double g_part[NPAIRS];

__device__ __forceinline__ const float* zptr(const float* X, const float* Y, int r) {
    return (r < N_HALF) ? (X + (size_t)r * DIM) : (Y + (size_t)(r - N_HALF) * DIM);
}

__device__ __forceinline__ float ex2f(float x) {
    float y;
    asm("ex2.approx.ftz.f32 %0, %1;" : "=f"(y) : "f"(x));
    return y;
}

// packed (x,x) for fp32x2 ops
__device__ __forceinline__ unsigned long long dupf(float x) {
    unsigned long long r;
    asm("mov.b64 %0, {%1, %1};" : "=l"(r) : "f"(x));
    return r;
}

__device__ __forceinline__ unsigned long long fma2(unsigned long long a,
                                                   unsigned long long b,
                                                   unsigned long long c) {
    unsigned long long d;
    asm("fma.rn.f32x2 %0, %1, %2, %3;" : "=l"(d) : "l"(a), "l"(b), "l"(c));
    return d;
}

__device__ __forceinline__ void unpack2(unsigned long long v, float& lo, float& hi) {
    asm("mov.b64 {%0, %1}, %2;" : "=f"(lo), "=f"(hi) : "l"(v));
}

// ---------------------------------------------------------------------------
// Pre-pass: row squared norms + partial column sums (one read of Z).
// grid=256 x 256 thr; block b owns rows [b*32, b*32+32).
// ---------------------------------------------------------------------------
__global__ void __launch_bounds__(256) k_pre(const float* __restrict__ X,
                                             const float* __restrict__ Y) {
    int t = threadIdx.x;
    int r0 = blockIdx.x * 32;

    // column partial sums (coalesced: thread t = column t)
    double acc = 0.0;
    #pragma unroll 4
    for (int r = 0; r < 32; r++)
        acc += (double)zptr(X, Y, r0 + r)[t];
    g_colpart[blockIdx.x * 256 + t] = acc;

    // row norms: 8 warps x 4 rows (rows now L2-hot)
    int warp = t >> 5, lane = t & 31;
    #pragma unroll
    for (int rr = 0; rr < 4; rr++) {
        int row = r0 + warp * 4 + rr;
        const float* zr = zptr(X, Y, row);
        float s = 0.f;
        #pragma unroll
        for (int c = lane; c < DIM; c += 32) {
            float v = zr[c];
            s = fmaf(v, v, s);
        }
        #pragma unroll
        for (int o = 16; o; o >>= 1) s += __shfl_xor_sync(0xffffffffu, s, o);
        if (lane == 0) g_snorm[row] = s;
    }
}

// ---------------------------------------------------------------------------
// Bandwidth -> exponent coefficient. Single block, deterministic.
// ---------------------------------------------------------------------------
__global__ void __launch_bounds__(256) k_bw() {
    __shared__ double sh[256];
    int t = threadIdx.x;

    double ss = 0.0;
    for (int i = t; i < N_TOT; i += 256) ss += (double)g_snorm[i];
    sh[t] = ss;
    __syncthreads();
    for (int o = 128; o; o >>= 1) {
        if (t < o) sh[t] += sh[t + o];
        __syncthreads();
    }
    double sum_s = sh[0];
    __syncthreads();

    double C = 0.0;
    for (int b = 0; b < 256; b++) C += g_colpart[b * 256 + t];
    sh[t] = C * C;
    __syncthreads();
    for (int o = 128; o; o >>= 1) {
        if (t < o) sh[t] += sh[t + o];
        __syncthreads();
    }
    if (t == 0) {
        double total = 2.0 * (double)N_TOT * sum_s - 2.0 * sh[0];
        double bw = total / ((double)N_TOT * (double)N_TOT - (double)N_TOT);
        g_coef = (float)(1.4426950408889634 / (4.0 * bw));
    }
}

// ---------------------------------------------------------------------------
// Main pairwise tile kernel. 2080 CTAs = upper-triangular tile pairs.
// 256 thr, 8x8 register tile per thread (as 8x4 fp32x2 pairs), BK=8,
// double-buffered smem, conflict-free split fragments.
// ---------------------------------------------------------------------------
__global__ void __launch_bounds__(256, 2) k_main(const float* __restrict__ X,
                                                 const float* __restrict__ Y) {
    __shared__ float As[2][BK][BM];
    __shared__ float Bs[2][BK][BM];
    __shared__ double red[256];

    // decode linear id -> (ti, tj), ti <= tj
    int L = blockIdx.x;
    int ti = (int)((129.0 - sqrt(16641.0 - 8.0 * (double)L)) * 0.5);
    if (ti > TILES - 1) ti = TILES - 1;
    if (ti < 0) ti = 0;
    while ((ti + 1) * (129 - (ti + 1)) / 2 <= L) ti++;
    while (ti * (129 - ti) / 2 > L) ti--;
    int tj = ti + (L - ti * (129 - ti) / 2);

    int tid = threadIdx.x;
    int tx = tid & 15, ty = tid >> 4;
    int lrow = tid >> 1;           // 0..127
    int lc4  = (tid & 1) << 2;     // 0 or 4
    const float* arow = zptr(X, Y, ti * BM + lrow) + lc4;
    const float* brow = zptr(X, Y, tj * BM + lrow) + lc4;

    unsigned long long acc2[8][4];
    #pragma unroll
    for (int u = 0; u < 8; u++)
        #pragma unroll
        for (int v = 0; v < 4; v++) acc2[u][v] = 0ull;

    float4 ap = *(const float4*)(arow);
    float4 bp = *(const float4*)(brow);
    As[0][lc4 + 0][lrow] = ap.x; As[0][lc4 + 1][lrow] = ap.y;
    As[0][lc4 + 2][lrow] = ap.z; As[0][lc4 + 3][lrow] = ap.w;
    Bs[0][lc4 + 0][lrow] = bp.x; Bs[0][lc4 + 1][lrow] = bp.y;
    Bs[0][lc4 + 2][lrow] = bp.z; Bs[0][lc4 + 3][lrow] = bp.w;
    __syncthreads();

    const int NIT = DIM / BK;      // 32
    for (int it = 0; it < NIT; it++) {
        int cur = it & 1;
        int nxt = cur ^ 1;
        bool more = (it + 1 < NIT);
        if (more) {                // prefetch next slab (L2-resident)
            ap = *(const float4*)(arow + (it + 1) * BK);
            bp = *(const float4*)(brow + (it + 1) * BK);
        }

        #pragma unroll
        for (int k = 0; k < BK; k++) {
            // split fragments: lanes cover all 32 banks per 128B phase -> no conflicts
            float4 a0 = *(const float4*)&As[cur][k][ty * 4];
            float4 a1 = *(const float4*)&As[cur][k][64 + ty * 4];
            ulonglong2 b0 = *(const ulonglong2*)&Bs[cur][k][tx * 4];
            ulonglong2 b1 = *(const ulonglong2*)&Bs[cur][k][64 + tx * 4];
            unsigned long long rb[4] = {b0.x, b0.y, b1.x, b1.y};
            float ra[8] = {a0.x, a0.y, a0.z, a0.w, a1.x, a1.y, a1.z, a1.w};
            #pragma unroll
            for (int u = 0; u < 8; u++) {
                unsigned long long ad = dupf(ra[u]);
                #pragma unroll
                for (int v = 0; v < 4; v++)
                    acc2[u][v] = fma2(ad, rb[v], acc2[u][v]);
            }
        }

        if (more) {
            As[nxt][lc4 + 0][lrow] = ap.x; As[nxt][lc4 + 1][lrow] = ap.y;
            As[nxt][lc4 + 2][lrow] = ap.z; As[nxt][lc4 + 3][lrow] = ap.w;
            Bs[nxt][lc4 + 0][lrow] = bp.x; Bs[nxt][lc4 + 1][lrow] = bp.y;
            Bs[nxt][lc4 + 2][lrow] = bp.z; Bs[nxt][lc4 + 3][lrow] = bp.w;
        }
        __syncthreads();
    }

    // Epilogue: d2 -> 5-kernel sum via ex2 + squaring chain.
    float sA[8], sB[8];
    #pragma unroll
    for (int u = 0; u < 8; u++) {
        int io = (u < 4) ? (ty * 4 + u) : (64 + ty * 4 + u - 4);
        sA[u] = g_snorm[ti * BM + io];
    }
    #pragma unroll
    for (int v = 0; v < 4; v++) {
        int jo = (v < 2) ? (tx * 4 + 2 * v) : (64 + tx * 4 + 2 * (v - 2));
        sB[2 * v]     = g_snorm[tj * BM + jo];
        sB[2 * v + 1] = g_snorm[tj * BM + jo + 1];
    }
    float c = g_coef;

    float psum = 0.f;
    #pragma unroll
    for (int u = 0; u < 8; u++) {
        #pragma unroll
        for (int v = 0; v < 4; v++) {
            float d0, d1;
            unpack2(acc2[u][v], d0, d1);
            float dd[2] = {d0, d1};
            #pragma unroll
            for (int h = 0; h < 2; h++) {
                float d2 = fmaf(-2.f, dd[h], sA[u] + sB[2 * v + h]);
                d2 = fmaxf(d2, 0.f);
                float e  = ex2f(-d2 * c);   // mult 4
                float t2 = e * e;           // mult 2
                float ks = e + t2;
                float t4 = t2 * t2;  ks += t4;   // mult 1
                float t8 = t4 * t4;  ks += t8;   // mult 1/2
                ks += t8 * t8;                   // mult 1/4
                psum += ks;
            }
        }
    }

    double w = ((ti < HALF_TILES) == (tj < HALF_TILES)) ? 1.0 : -1.0;
    if (ti != tj) w *= 2.0;

    red[tid] = (double)psum * w;
    __syncthreads();
    for (int o = 128; o; o >>= 1) {
        if (tid < o) red[tid] += red[tid + o];
        __syncthreads();
    }
    if (tid == 0) g_part[L] = red[0];
}

// ---------------------------------------------------------------------------
// Final deterministic reduction + scale.
// ---------------------------------------------------------------------------
__global__ void __launch_bounds__(256) k_final(float* __restrict__ out) {
    __shared__ double sh[256];
    int t = threadIdx.x;
    double a = 0.0;
    for (int i = t; i < NPAIRS; i += 256) a += g_part[i];
    sh[t] = a;
    __syncthreads();
    for (int o = 128; o; o >>= 1) {
        if (t < o) sh[t] += sh[t + o];
        __syncthreads();
    }
    if (t == 0)
        out[0] = (float)(sh[0] / ((double)N_HALF * (double)N_HALF));
}

extern "C" void kernel_launch(void* const* d_in, const int* in_sizes, int n_in,
                              void* d_out, int out_size) {
    const float* X = (const float*)d_in[0];
    const float* Y = (const float*)d_in[1];
    float* out = (float*)d_out;
    (void)in_sizes; (void)n_in; (void)out_size;

    k_pre<<<256, 256>>>(X, Y);
    k_bw<<<1, 256>>>();
    k_main<<<NPAIRS, 256>>>(X, Y);
    k_final<<<1, 256>>>(out);
}

// round 5
// speedup vs baseline: 2.2386x; 1.7476x over previous
#include <cuda_runtime.h>
#include <cstdint>

// MMD loss via tf32 mma.sync GEMM (compute_103-safe; no tcgen05).
//   Z -> tf32-rounded copy g_ztf (cvt.rna). dot via m16n8k8 tf32 MMA, fp32 accum.
//   d2 = s_i + s_j - 2 dot ; bw analytic ; K = 5-kernel sum via ex2 + squarings.
//   Triangular tile launch (2080 CTAs x 256 thr), 128x128 tile, BK=32, K=256.

#define N_HALF 4096
#define N_TOT  8192
#define DIM    256
#define BM     128
#define BK     32
#define TILES  64
#define HALF_TILES 32
#define NPAIRS 2080
#define LDA    36            // padded smem row stride in floats (bank-conflict-free)

// dynamic smem float offsets
#define OFF_A0 0
#define OFF_A1 4608
#define OFF_B0 9216
#define OFF_B1 13824
#define OFF_SA 18432
#define OFF_SBN 18560
#define OFF_RED 18688        // byte 74752, 8-aligned
#define SMEM_BYTES (74752 + 64)

__device__ float  g_ztf[(size_t)N_TOT * DIM];
__device__ float  g_snorm[N_TOT];
__device__ double g_colpart[256 * 256];
__device__ float  g_coef;             // log2(e)/(4*bw)
__device__ double g_part[NPAIRS];

__device__ __forceinline__ const float* zptr(const float* X, const float* Y, int r) {
    return (r < N_HALF) ? (X + (size_t)r * DIM) : (Y + (size_t)(r - N_HALF) * DIM);
}

__device__ __forceinline__ float ex2f(float x) {
    float y; asm("ex2.approx.ftz.f32 %0, %1;" : "=f"(y) : "f"(x)); return y;
}

__device__ __forceinline__ void mma_tf32(float* c, uint32_t a0, uint32_t a1,
                                         uint32_t a2, uint32_t a3,
                                         uint32_t b0, uint32_t b1) {
    asm volatile(
        "mma.sync.aligned.m16n8k8.row.col.f32.tf32.tf32.f32 "
        "{%0,%1,%2,%3}, {%4,%5,%6,%7}, {%8,%9}, {%0,%1,%2,%3};"
        : "+f"(c[0]), "+f"(c[1]), "+f"(c[2]), "+f"(c[3])
        : "r"(a0), "r"(a1), "r"(a2), "r"(a3), "r"(b0), "r"(b1));
}

// ---------------------------------------------------------------------------
// Pre-pass: tf32-rounded copy + column partial sums + row squared norms.
// grid=256 x 256 thr; block b owns rows [b*32, b*32+32).
// ---------------------------------------------------------------------------
__global__ void __launch_bounds__(256) k_pre(const float* __restrict__ X,
                                             const float* __restrict__ Y) {
    int t = threadIdx.x;
    int r0 = blockIdx.x * 32;

    double acc = 0.0;
    #pragma unroll 4
    for (int r = 0; r < 32; r++) {
        int row = r0 + r;
        float v = zptr(X, Y, row)[t];
        acc += (double)v;
        uint32_t tf;
        asm("cvt.rna.tf32.f32 %0, %1;" : "=r"(tf) : "f"(v));
        g_ztf[(size_t)row * DIM + t] = __uint_as_float(tf);
    }
    g_colpart[blockIdx.x * 256 + t] = acc;

    int warp = t >> 5, lane = t & 31;
    #pragma unroll
    for (int rr = 0; rr < 4; rr++) {
        int row = r0 + warp * 4 + rr;
        const float* zr = zptr(X, Y, row);
        float s = 0.f;
        #pragma unroll
        for (int c = lane; c < DIM; c += 32) { float v = zr[c]; s = fmaf(v, v, s); }
        #pragma unroll
        for (int o = 16; o; o >>= 1) s += __shfl_xor_sync(0xffffffffu, s, o);
        if (lane == 0) g_snorm[row] = s;
    }
}

// ---------------------------------------------------------------------------
// Bandwidth -> exponent coefficient. Single block, deterministic.
// ---------------------------------------------------------------------------
__global__ void __launch_bounds__(256) k_bw() {
    __shared__ double sh[256];
    int t = threadIdx.x;
    double ss = 0.0;
    for (int i = t; i < N_TOT; i += 256) ss += (double)g_snorm[i];
    sh[t] = ss; __syncthreads();
    for (int o = 128; o; o >>= 1) { if (t < o) sh[t] += sh[t + o]; __syncthreads(); }
    double sum_s = sh[0];
    __syncthreads();
    double C = 0.0;
    for (int b = 0; b < 256; b++) C += g_colpart[b * 256 + t];
    sh[t] = C * C; __syncthreads();
    for (int o = 128; o; o >>= 1) { if (t < o) sh[t] += sh[t + o]; __syncthreads(); }
    if (t == 0) {
        double total = 2.0 * (double)N_TOT * sum_s - 2.0 * sh[0];
        double bw = total / ((double)N_TOT * (double)N_TOT - (double)N_TOT);
        g_coef = (float)(1.4426950408889634 / (4.0 * bw));
    }
}

// ---------------------------------------------------------------------------
// Main: one 128x128 tile-pair per CTA; tf32 mma.sync; exp epilogue on frags.
// 8 warps as 2(m) x 4(n); each warp: 64x32 region = 4x4 m16n8 tiles.
// ---------------------------------------------------------------------------
__global__ void __launch_bounds__(256) k_main() {
    extern __shared__ float sm[];
    float* Abuf[2] = { sm + OFF_A0, sm + OFF_A1 };
    float* Bbuf[2] = { sm + OFF_B0, sm + OFF_B1 };
    float* sA  = sm + OFF_SA;
    float* sBn = sm + OFF_SBN;
    double* red = (double*)(sm + OFF_RED);

    int tid = threadIdx.x, lane = tid & 31, wid = tid >> 5;

    // decode linear id -> (ti, tj), ti <= tj
    int L = blockIdx.x;
    int ti = (int)((129.0 - sqrt(16641.0 - 8.0 * (double)L)) * 0.5);
    if (ti > TILES - 1) ti = TILES - 1;
    if (ti < 0) ti = 0;
    while ((ti + 1) * (129 - (ti + 1)) / 2 <= L) ti++;
    while (ti * (129 - ti) / 2 > L) ti--;
    int tj = ti + (L - ti * (129 - ti) / 2);

    const float* Ag = g_ztf + (size_t)ti * BM * DIM;
    const float* Bg = g_ztf + (size_t)tj * BM * DIM;

    if (tid < 128) sA[tid] = g_snorm[ti * BM + tid];
    else           sBn[tid - 128] = g_snorm[tj * BM + tid - 128];

    // prefetch iteration 0
    float4 pa[4], pb[4];
    #pragma unroll
    for (int q = 0; q < 4; q++) {
        int idx = q * 256 + tid;
        int row = idx >> 3, c4 = (idx & 7) * 4;
        pa[q] = *(const float4*)(Ag + row * DIM + c4);
        pb[q] = *(const float4*)(Bg + row * DIM + c4);
    }
    #pragma unroll
    for (int q = 0; q < 4; q++) {
        int idx = q * 256 + tid;
        int row = idx >> 3, c4 = (idx & 7) * 4;
        float* da = Abuf[0] + row * LDA + c4;
        float* db = Bbuf[0] + row * LDA + c4;
        *(float2*)(da)     = make_float2(pa[q].x, pa[q].y);
        *(float2*)(da + 2) = make_float2(pa[q].z, pa[q].w);
        *(float2*)(db)     = make_float2(pb[q].x, pb[q].y);
        *(float2*)(db + 2) = make_float2(pb[q].z, pb[q].w);
    }
    __syncthreads();

    float acc[16][4];
    #pragma unroll
    for (int i = 0; i < 16; i++)
        #pragma unroll
        for (int j = 0; j < 4; j++) acc[i][j] = 0.f;

    int wm = wid >> 2, wn = wid & 3;
    int g = lane >> 2, cq = lane & 3;
    int aoff = (wm * 64 + g) * LDA + cq;
    int boff = (wn * 32 + g) * LDA + cq;

    const int NIT = DIM / BK;   // 8
    for (int it = 0; it < NIT; it++) {
        int cur = it & 1;
        bool more = (it + 1 < NIT);
        if (more) {
            int k0 = (it + 1) * BK;
            #pragma unroll
            for (int q = 0; q < 4; q++) {
                int idx = q * 256 + tid;
                int row = idx >> 3, c4 = (idx & 7) * 4;
                pa[q] = *(const float4*)(Ag + row * DIM + k0 + c4);
                pb[q] = *(const float4*)(Bg + row * DIM + k0 + c4);
            }
        }

        const float* Ac = Abuf[cur];
        const float* Bc = Bbuf[cur];
        #pragma unroll
        for (int ks = 0; ks < 4; ks++) {
            int kc = ks * 8;
            uint32_t bf[4][2];
            #pragma unroll
            for (int nt = 0; nt < 4; nt++) {
                bf[nt][0] = __float_as_uint(Bc[boff + nt * 8 * LDA + kc]);
                bf[nt][1] = __float_as_uint(Bc[boff + nt * 8 * LDA + kc + 4]);
            }
            #pragma unroll
            for (int mt = 0; mt < 4; mt++) {
                uint32_t a0 = __float_as_uint(Ac[aoff + (mt * 16)     * LDA + kc]);
                uint32_t a1 = __float_as_uint(Ac[aoff + (mt * 16 + 8) * LDA + kc]);
                uint32_t a2 = __float_as_uint(Ac[aoff + (mt * 16)     * LDA + kc + 4]);
                uint32_t a3 = __float_as_uint(Ac[aoff + (mt * 16 + 8) * LDA + kc + 4]);
                #pragma unroll
                for (int nt = 0; nt < 4; nt++)
                    mma_tf32(acc[mt * 4 + nt], a0, a1, a2, a3, bf[nt][0], bf[nt][1]);
            }
        }

        if (more) {
            int nxt = cur ^ 1;
            #pragma unroll
            for (int q = 0; q < 4; q++) {
                int idx = q * 256 + tid;
                int row = idx >> 3, c4 = (idx & 7) * 4;
                float* da = Abuf[nxt] + row * LDA + c4;
                float* db = Bbuf[nxt] + row * LDA + c4;
                *(float2*)(da)     = make_float2(pa[q].x, pa[q].y);
                *(float2*)(da + 2) = make_float2(pa[q].z, pa[q].w);
                *(float2*)(db)     = make_float2(pb[q].x, pb[q].y);
                *(float2*)(db + 2) = make_float2(pb[q].z, pb[q].w);
            }
        }
        __syncthreads();
    }

    // Epilogue on register fragments.
    float c = g_coef;
    float twoC = 2.f * c;
    float rA[8], cB[8];
    #pragma unroll
    for (int mt = 0; mt < 4; mt++) {
        rA[mt * 2 + 0] = sA[wm * 64 + mt * 16 + g]     * c;
        rA[mt * 2 + 1] = sA[wm * 64 + mt * 16 + g + 8] * c;
    }
    #pragma unroll
    for (int nt = 0; nt < 4; nt++) {
        cB[nt * 2 + 0] = sBn[wn * 32 + nt * 8 + cq * 2]     * c;
        cB[nt * 2 + 1] = sBn[wn * 32 + nt * 8 + cq * 2 + 1] * c;
    }

    float psum = 0.f;
    #pragma unroll
    for (int mt = 0; mt < 4; mt++) {
        #pragma unroll
        for (int nt = 0; nt < 4; nt++) {
            float* cc = acc[mt * 4 + nt];
            #pragma unroll
            for (int u = 0; u < 4; u++) {
                int h = u >> 1, e = u & 1;
                float arg = fmaf(cc[u], twoC, -(rA[mt * 2 + h] + cB[nt * 2 + e]));
                arg = fminf(arg, 0.f);           // d2 clamp
                float ee = ex2f(arg);            // mult 4
                float t2 = ee * ee;              // mult 2
                float ks = ee + t2;
                float t4 = t2 * t2;  ks += t4;   // mult 1
                float t8 = t4 * t4;  ks += t8;   // mult 1/2
                ks = fmaf(t8, t8, ks);           // mult 1/4
                psum += ks;
            }
        }
    }

    double wsum = (double)psum;
    #pragma unroll
    for (int o = 16; o; o >>= 1) wsum += __shfl_xor_sync(0xffffffffu, wsum, o);
    if (lane == 0) red[wid] = wsum;
    __syncthreads();
    if (tid == 0) {
        double s = 0.0;
        #pragma unroll
        for (int w = 0; w < 8; w++) s += red[w];
        double wgt = ((ti < HALF_TILES) == (tj < HALF_TILES)) ? 1.0 : -1.0;
        if (ti != tj) wgt *= 2.0;
        g_part[L] = s * wgt;
    }
}

// ---------------------------------------------------------------------------
// Final deterministic reduction + scale.
// ---------------------------------------------------------------------------
__global__ void __launch_bounds__(256) k_final(float* __restrict__ out) {
    __shared__ double sh[256];
    int t = threadIdx.x;
    double a = 0.0;
    for (int i = t; i < NPAIRS; i += 256) a += g_part[i];
    sh[t] = a; __syncthreads();
    for (int o = 128; o; o >>= 1) { if (t < o) sh[t] += sh[t + o]; __syncthreads(); }
    if (t == 0)
        out[0] = (float)(sh[0] / ((double)N_HALF * (double)N_HALF));
}

extern "C" void kernel_launch(void* const* d_in, const int* in_sizes, int n_in,
                              void* d_out, int out_size) {
    const float* X = (const float*)d_in[0];
    const float* Y = (const float*)d_in[1];
    float* out = (float*)d_out;
    (void)in_sizes; (void)n_in; (void)out_size;

    cudaFuncSetAttribute(k_main, cudaFuncAttributeMaxDynamicSharedMemorySize, SMEM_BYTES);

    k_pre<<<256, 256>>>(X, Y);
    k_bw<<<1, 256>>>();
    k_main<<<NPAIRS, 256, SMEM_BYTES>>>();
    k_final<<<1, 256>>>(out);
}

// round 6
// speedup vs baseline: 2.6685x; 1.1921x over previous
#include <cuda_runtime.h>
#include <cstdint>

// MMD loss via tf32 mma.sync GEMM (compute_103-safe; no tcgen05).
//   Z -> tf32-rounded copy g_ztf (cvt.rna). dot via m16n8k8 tf32 MMA, fp32 accum.
//   d2 = s_i + s_j - 2 dot ; bw analytic ; K = 5-kernel sum via ex2 + squarings.
//   Triangular tile launch (2080 CTAs x 256 thr), 128x128 tile, BK=32, K=256.
//   cp.async double-buffered smem, 2 CTAs/SM.

#define N_HALF 4096
#define N_TOT  8192
#define DIM    256
#define BM     128
#define BK     32
#define TILES  64
#define HALF_TILES 32
#define NPAIRS 2080
#define LDA    36            // padded smem row stride in floats (bank-conflict-free)

// dynamic smem float offsets
#define OFF_A0 0
#define OFF_A1 4608
#define OFF_B0 9216
#define OFF_B1 13824
#define OFF_SA 18432
#define OFF_SBN 18560
#define OFF_RED 18688        // byte 74752, 8-aligned
#define SMEM_BYTES (74752 + 64)

__device__ float  g_ztf[(size_t)N_TOT * DIM];
__device__ float  g_snorm[N_TOT];
__device__ double g_colpart[256 * 256];
__device__ float  g_coef;             // log2(e)/(4*bw)
__device__ double g_part[NPAIRS];

__device__ __forceinline__ const float* zptr(const float* X, const float* Y, int r) {
    return (r < N_HALF) ? (X + (size_t)r * DIM) : (Y + (size_t)(r - N_HALF) * DIM);
}

__device__ __forceinline__ float ex2f(float x) {
    float y; asm("ex2.approx.ftz.f32 %0, %1;" : "=f"(y) : "f"(x)); return y;
}

__device__ __forceinline__ uint32_t smem_u32(const void* p) {
    uint32_t a;
    asm("{ .reg .u64 t; cvta.to.shared.u64 t, %1; cvt.u32.u64 %0, t; }" : "=r"(a) : "l"(p));
    return a;
}

__device__ __forceinline__ void cp16(uint32_t dst, const void* src) {
    asm volatile("cp.async.cg.shared.global [%0], [%1], 16;" :: "r"(dst), "l"(src));
}

__device__ __forceinline__ void mma_tf32(float* c, uint32_t a0, uint32_t a1,
                                         uint32_t a2, uint32_t a3,
                                         uint32_t b0, uint32_t b1) {
    asm volatile(
        "mma.sync.aligned.m16n8k8.row.col.f32.tf32.tf32.f32 "
        "{%0,%1,%2,%3}, {%4,%5,%6,%7}, {%8,%9}, {%0,%1,%2,%3};"
        : "+f"(c[0]), "+f"(c[1]), "+f"(c[2]), "+f"(c[3])
        : "r"(a0), "r"(a1), "r"(a2), "r"(a3), "r"(b0), "r"(b1));
}

// ---------------------------------------------------------------------------
// Pre-pass: tf32-rounded copy + column partial sums + row squared norms.
// ---------------------------------------------------------------------------
__global__ void __launch_bounds__(256) k_pre(const float* __restrict__ X,
                                             const float* __restrict__ Y) {
    int t = threadIdx.x;
    int r0 = blockIdx.x * 32;

    double acc = 0.0;
    #pragma unroll 4
    for (int r = 0; r < 32; r++) {
        int row = r0 + r;
        float v = zptr(X, Y, row)[t];
        acc += (double)v;
        uint32_t tf;
        asm("cvt.rna.tf32.f32 %0, %1;" : "=r"(tf) : "f"(v));
        g_ztf[(size_t)row * DIM + t] = __uint_as_float(tf);
    }
    g_colpart[blockIdx.x * 256 + t] = acc;

    int warp = t >> 5, lane = t & 31;
    #pragma unroll
    for (int rr = 0; rr < 4; rr++) {
        int row = r0 + warp * 4 + rr;
        const float* zr = zptr(X, Y, row);
        float s = 0.f;
        #pragma unroll
        for (int c = lane; c < DIM; c += 32) { float v = zr[c]; s = fmaf(v, v, s); }
        #pragma unroll
        for (int o = 16; o; o >>= 1) s += __shfl_xor_sync(0xffffffffu, s, o);
        if (lane == 0) g_snorm[row] = s;
    }
}

// ---------------------------------------------------------------------------
// Bandwidth -> exponent coefficient. Single block, deterministic.
// ---------------------------------------------------------------------------
__global__ void __launch_bounds__(256) k_bw() {
    __shared__ double sh[256];
    int t = threadIdx.x;
    double ss = 0.0;
    for (int i = t; i < N_TOT; i += 256) ss += (double)g_snorm[i];
    sh[t] = ss; __syncthreads();
    for (int o = 128; o; o >>= 1) { if (t < o) sh[t] += sh[t + o]; __syncthreads(); }
    double sum_s = sh[0];
    __syncthreads();
    double C = 0.0;
    for (int b = 0; b < 256; b++) C += g_colpart[b * 256 + t];
    sh[t] = C * C; __syncthreads();
    for (int o = 128; o; o >>= 1) { if (t < o) sh[t] += sh[t + o]; __syncthreads(); }
    if (t == 0) {
        double total = 2.0 * (double)N_TOT * sum_s - 2.0 * sh[0];
        double bw = total / ((double)N_TOT * (double)N_TOT - (double)N_TOT);
        g_coef = (float)(1.4426950408889634 / (4.0 * bw));
    }
}

// ---------------------------------------------------------------------------
// Main: one 128x128 tile-pair per CTA; tf32 mma.sync; cp.async pipeline.
// 8 warps as 2(m) x 4(n); each warp: 64x32 region = 4x4 m16n8 tiles.
// ---------------------------------------------------------------------------
__global__ void __launch_bounds__(256, 2) k_main() {
    extern __shared__ float sm[];
    float* sA  = sm + OFF_SA;
    float* sBn = sm + OFF_SBN;
    double* red = (double*)(sm + OFF_RED);

    int tid = threadIdx.x, lane = tid & 31, wid = tid >> 5;

    // decode linear id -> (ti, tj), ti <= tj
    int L = blockIdx.x;
    int ti = (int)((129.0 - sqrt(16641.0 - 8.0 * (double)L)) * 0.5);
    if (ti > TILES - 1) ti = TILES - 1;
    if (ti < 0) ti = 0;
    while ((ti + 1) * (129 - (ti + 1)) / 2 <= L) ti++;
    while (ti * (129 - ti) / 2 > L) ti--;
    int tj = ti + (L - ti * (129 - ti) / 2);

    const float* Ag = g_ztf + (size_t)ti * BM * DIM;
    const float* Bg = g_ztf + (size_t)tj * BM * DIM;

    if (tid < 128) sA[tid] = g_snorm[ti * BM + tid];
    else           sBn[tid - 128] = g_snorm[tj * BM + tid - 128];

    // per-thread cp.async source/dest (4 x 16B chunks per matrix per buffer)
    int idx0 = tid;                 // q*256 + tid, q=0..3
    uint32_t smA[2] = { smem_u32(sm + OFF_A0), smem_u32(sm + OFF_A1) };
    uint32_t smB[2] = { smem_u32(sm + OFF_B0), smem_u32(sm + OFF_B1) };

    #define ISSUE(buf, k0)                                                     \
        {                                                                      \
            _Pragma("unroll")                                                  \
            for (int q = 0; q < 4; q++) {                                      \
                int idx = q * 256 + idx0;                                      \
                int row = idx >> 3, c4 = (idx & 7) * 4;                        \
                uint32_t doff = (uint32_t)(row * LDA + c4) * 4u;               \
                cp16(smA[buf] + doff, Ag + (size_t)row * DIM + (k0) + c4);     \
                cp16(smB[buf] + doff, Bg + (size_t)row * DIM + (k0) + c4);     \
            }                                                                  \
            asm volatile("cp.async.commit_group;" ::: "memory");               \
        }

    ISSUE(0, 0)

    float acc[16][4];
    #pragma unroll
    for (int i = 0; i < 16; i++)
        #pragma unroll
        for (int j = 0; j < 4; j++) acc[i][j] = 0.f;

    int wm = wid >> 2, wn = wid & 3;
    int g = lane >> 2, cq = lane & 3;
    int aoff = (wm * 64 + g) * LDA + cq;
    int boff = (wn * 32 + g) * LDA + cq;

    const int NIT = DIM / BK;   // 8
    for (int it = 0; it < NIT; it++) {
        int cur = it & 1;
        bool more = (it + 1 < NIT);
        if (more) ISSUE(cur ^ 1, (it + 1) * BK)

        if (more) asm volatile("cp.async.wait_group 1;" ::: "memory");
        else      asm volatile("cp.async.wait_group 0;" ::: "memory");
        __syncthreads();

        const float* Ac = sm + (cur ? OFF_A1 : OFF_A0);
        const float* Bc = sm + (cur ? OFF_B1 : OFF_B0);
        #pragma unroll
        for (int ks = 0; ks < 4; ks++) {
            int kc = ks * 8;
            uint32_t bf[4][2];
            #pragma unroll
            for (int nt = 0; nt < 4; nt++) {
                bf[nt][0] = __float_as_uint(Bc[boff + nt * 8 * LDA + kc]);
                bf[nt][1] = __float_as_uint(Bc[boff + nt * 8 * LDA + kc + 4]);
            }
            #pragma unroll
            for (int mt = 0; mt < 4; mt++) {
                uint32_t a0 = __float_as_uint(Ac[aoff + (mt * 16)     * LDA + kc]);
                uint32_t a1 = __float_as_uint(Ac[aoff + (mt * 16 + 8) * LDA + kc]);
                uint32_t a2 = __float_as_uint(Ac[aoff + (mt * 16)     * LDA + kc + 4]);
                uint32_t a3 = __float_as_uint(Ac[aoff + (mt * 16 + 8) * LDA + kc + 4]);
                #pragma unroll
                for (int nt = 0; nt < 4; nt++)
                    mma_tf32(acc[mt * 4 + nt], a0, a1, a2, a3, bf[nt][0], bf[nt][1]);
            }
        }
        __syncthreads();
    }

    // Epilogue on register fragments.
    float c = g_coef;
    float twoC = 2.f * c;
    float rA[8], cB[8];
    #pragma unroll
    for (int mt = 0; mt < 4; mt++) {
        rA[mt * 2 + 0] = sA[wm * 64 + mt * 16 + g]     * c;
        rA[mt * 2 + 1] = sA[wm * 64 + mt * 16 + g + 8] * c;
    }
    #pragma unroll
    for (int nt = 0; nt < 4; nt++) {
        cB[nt * 2 + 0] = sBn[wn * 32 + nt * 8 + cq * 2]     * c;
        cB[nt * 2 + 1] = sBn[wn * 32 + nt * 8 + cq * 2 + 1] * c;
    }

    float psum = 0.f;
    #pragma unroll
    for (int mt = 0; mt < 4; mt++) {
        #pragma unroll
        for (int nt = 0; nt < 4; nt++) {
            float* cc = acc[mt * 4 + nt];
            #pragma unroll
            for (int u = 0; u < 4; u++) {
                int h = u >> 1, e = u & 1;
                float arg = fmaf(cc[u], twoC, -(rA[mt * 2 + h] + cB[nt * 2 + e]));
                arg = fminf(arg, 0.f);           // d2 clamp
                float ee = ex2f(arg);            // mult 4
                float t2 = ee * ee;              // mult 2
                float ks = ee + t2;
                float t4 = t2 * t2;  ks += t4;   // mult 1
                float t8 = t4 * t4;  ks += t8;   // mult 1/2
                ks = fmaf(t8, t8, ks);           // mult 1/4
                psum += ks;
            }
        }
    }

    double wsum = (double)psum;
    #pragma unroll
    for (int o = 16; o; o >>= 1) wsum += __shfl_xor_sync(0xffffffffu, wsum, o);
    if (lane == 0) red[wid] = wsum;
    __syncthreads();
    if (tid == 0) {
        double s = 0.0;
        #pragma unroll
        for (int w = 0; w < 8; w++) s += red[w];
        double wgt = ((ti < HALF_TILES) == (tj < HALF_TILES)) ? 1.0 : -1.0;
        if (ti != tj) wgt *= 2.0;
        g_part[L] = s * wgt;
    }
}

// ---------------------------------------------------------------------------
// Final deterministic reduction + scale.
// ---------------------------------------------------------------------------
__global__ void __launch_bounds__(256) k_final(float* __restrict__ out) {
    __shared__ double sh[256];
    int t = threadIdx.x;
    double a = 0.0;
    for (int i = t; i < NPAIRS; i += 256) a += g_part[i];
    sh[t] = a; __syncthreads();
    for (int o = 128; o; o >>= 1) { if (t < o) sh[t] += sh[t + o]; __syncthreads(); }
    if (t == 0)
        out[0] = (float)(sh[0] / ((double)N_HALF * (double)N_HALF));
}

extern "C" void kernel_launch(void* const* d_in, const int* in_sizes, int n_in,
                              void* d_out, int out_size) {
    const float* X = (const float*)d_in[0];
    const float* Y = (const float*)d_in[1];
    float* out = (float*)d_out;
    (void)in_sizes; (void)n_in; (void)out_size;

    cudaFuncSetAttribute(k_main, cudaFuncAttributeMaxDynamicSharedMemorySize, SMEM_BYTES);

    k_pre<<<256, 256>>>(X, Y);
    k_bw<<<1, 256>>>();
    k_main<<<NPAIRS, 256, SMEM_BYTES>>>();
    k_final<<<1, 256>>>(out);
}

// round 7
// speedup vs baseline: 2.6777x; 1.0034x over previous
#include <cuda_runtime.h>
#include <cstdint>

// MMD loss via tf32 mma.sync GEMM (compute_103-safe; no tcgen05).
//   Z -> tf32-rounded copy g_ztf (cvt.rna). dot via m16n8k8 tf32 MMA, fp32 accum.
//   d2 = s_i + s_j - 2 dot ; bw analytic ; K = 5-kernel sum via ex2 + squarings.
//   Triangular tile launch (2080 CTAs x 256 thr), 128x128 tile, BK=32, K=256.
//   cp.async double-buffered smem, 2 CTAs/SM.

#define N_HALF 4096
#define N_TOT  8192
#define DIM    256
#define BM     128
#define BK     32
#define TILES  64
#define HALF_TILES 32
#define NPAIRS 2080
#define LDA    36            // padded smem row stride in floats (bank-conflict-free)

// dynamic smem float offsets
#define OFF_A0 0
#define OFF_A1 4608
#define OFF_B0 9216
#define OFF_B1 13824
#define OFF_SA 18432
#define OFF_SBN 18560
#define OFF_RED 18688        // byte 74752, 8-aligned
#define SMEM_BYTES (74752 + 64)

__device__ float  g_ztf[(size_t)N_TOT * DIM];
__device__ float  g_snorm[N_TOT];
__device__ double g_colpart[256 * 256];
__device__ float  g_coef;             // log2(e)/(4*bw)
__device__ double g_part[NPAIRS];

__device__ __forceinline__ const float* zptr(const float* X, const float* Y, int r) {
    return (r < N_HALF) ? (X + (size_t)r * DIM) : (Y + (size_t)(r - N_HALF) * DIM);
}

__device__ __forceinline__ float ex2f(float x) {
    float y; asm("ex2.approx.ftz.f32 %0, %1;" : "=f"(y) : "f"(x)); return y;
}

__device__ __forceinline__ uint32_t smem_u32(const void* p) {
    uint32_t a;
    asm("{ .reg .u64 t; cvta.to.shared.u64 t, %1; cvt.u32.u64 %0, t; }" : "=r"(a) : "l"(p));
    return a;
}

__device__ __forceinline__ void cp16(uint32_t dst, const void* src) {
    asm volatile("cp.async.cg.shared.global [%0], [%1], 16;" :: "r"(dst), "l"(src));
}

__device__ __forceinline__ void mma_tf32(float* c, uint32_t a0, uint32_t a1,
                                         uint32_t a2, uint32_t a3,
                                         uint32_t b0, uint32_t b1) {
    asm volatile(
        "mma.sync.aligned.m16n8k8.row.col.f32.tf32.tf32.f32 "
        "{%0,%1,%2,%3}, {%4,%5,%6,%7}, {%8,%9}, {%0,%1,%2,%3};"
        : "+f"(c[0]), "+f"(c[1]), "+f"(c[2]), "+f"(c[3])
        : "r"(a0), "r"(a1), "r"(a2), "r"(a3), "r"(b0), "r"(b1));
}

// ---------------------------------------------------------------------------
// Pre-pass: tf32-rounded copy + column partial sums + row squared norms.
// ---------------------------------------------------------------------------
__global__ void __launch_bounds__(256) k_pre(const float* __restrict__ X,
                                             const float* __restrict__ Y) {
    int t = threadIdx.x;
    int r0 = blockIdx.x * 32;

    double acc = 0.0;
    #pragma unroll 4
    for (int r = 0; r < 32; r++) {
        int row = r0 + r;
        float v = zptr(X, Y, row)[t];
        acc += (double)v;
        uint32_t tf;
        asm("cvt.rna.tf32.f32 %0, %1;" : "=r"(tf) : "f"(v));
        g_ztf[(size_t)row * DIM + t] = __uint_as_float(tf);
    }
    g_colpart[blockIdx.x * 256 + t] = acc;

    int warp = t >> 5, lane = t & 31;
    #pragma unroll
    for (int rr = 0; rr < 4; rr++) {
        int row = r0 + warp * 4 + rr;
        const float* zr = zptr(X, Y, row);
        float s = 0.f;
        #pragma unroll
        for (int c = lane; c < DIM; c += 32) { float v = zr[c]; s = fmaf(v, v, s); }
        #pragma unroll
        for (int o = 16; o; o >>= 1) s += __shfl_xor_sync(0xffffffffu, s, o);
        if (lane == 0) g_snorm[row] = s;
    }
}

// ---------------------------------------------------------------------------
// Bandwidth -> exponent coefficient. Single block, deterministic.
// ---------------------------------------------------------------------------
__global__ void __launch_bounds__(256) k_bw() {
    __shared__ double sh[256];
    int t = threadIdx.x;
    double ss = 0.0;
    for (int i = t; i < N_TOT; i += 256) ss += (double)g_snorm[i];
    sh[t] = ss; __syncthreads();
    for (int o = 128; o; o >>= 1) { if (t < o) sh[t] += sh[t + o]; __syncthreads(); }
    double sum_s = sh[0];
    __syncthreads();
    double C = 0.0;
    for (int b = 0; b < 256; b++) C += g_colpart[b * 256 + t];
    sh[t] = C * C; __syncthreads();
    for (int o = 128; o; o >>= 1) { if (t < o) sh[t] += sh[t + o]; __syncthreads(); }
    if (t == 0) {
        double total = 2.0 * (double)N_TOT * sum_s - 2.0 * sh[0];
        double bw = total / ((double)N_TOT * (double)N_TOT - (double)N_TOT);
        g_coef = (float)(1.4426950408889634 / (4.0 * bw));
    }
}

// ---------------------------------------------------------------------------
// Main: one 128x128 tile-pair per CTA; tf32 mma.sync; cp.async pipeline.
// 8 warps as 2(m) x 4(n); each warp: 64x32 region = 4x4 m16n8 tiles.
// ---------------------------------------------------------------------------
__global__ void __launch_bounds__(256, 2) k_main() {
    extern __shared__ float sm[];
    float* sA  = sm + OFF_SA;
    float* sBn = sm + OFF_SBN;
    double* red = (double*)(sm + OFF_RED);

    int tid = threadIdx.x, lane = tid & 31, wid = tid >> 5;

    // decode linear id -> (ti, tj), ti <= tj
    int L = blockIdx.x;
    int ti = (int)((129.0 - sqrt(16641.0 - 8.0 * (double)L)) * 0.5);
    if (ti > TILES - 1) ti = TILES - 1;
    if (ti < 0) ti = 0;
    while ((ti + 1) * (129 - (ti + 1)) / 2 <= L) ti++;
    while (ti * (129 - ti) / 2 > L) ti--;
    int tj = ti + (L - ti * (129 - ti) / 2);

    const float* Ag = g_ztf + (size_t)ti * BM * DIM;
    const float* Bg = g_ztf + (size_t)tj * BM * DIM;

    if (tid < 128) sA[tid] = g_snorm[ti * BM + tid];
    else           sBn[tid - 128] = g_snorm[tj * BM + tid - 128];

    // per-thread cp.async source/dest (4 x 16B chunks per matrix per buffer)
    int idx0 = tid;                 // q*256 + tid, q=0..3
    uint32_t smA[2] = { smem_u32(sm + OFF_A0), smem_u32(sm + OFF_A1) };
    uint32_t smB[2] = { smem_u32(sm + OFF_B0), smem_u32(sm + OFF_B1) };

    #define ISSUE(buf, k0)                                                     \
        {                                                                      \
            _Pragma("unroll")                                                  \
            for (int q = 0; q < 4; q++) {                                      \
                int idx = q * 256 + idx0;                                      \
                int row = idx >> 3, c4 = (idx & 7) * 4;                        \
                uint32_t doff = (uint32_t)(row * LDA + c4) * 4u;               \
                cp16(smA[buf] + doff, Ag + (size_t)row * DIM + (k0) + c4);     \
                cp16(smB[buf] + doff, Bg + (size_t)row * DIM + (k0) + c4);     \
            }                                                                  \
            asm volatile("cp.async.commit_group;" ::: "memory");               \
        }

    ISSUE(0, 0)

    float acc[16][4];
    #pragma unroll
    for (int i = 0; i < 16; i++)
        #pragma unroll
        for (int j = 0; j < 4; j++) acc[i][j] = 0.f;

    int wm = wid >> 2, wn = wid & 3;
    int g = lane >> 2, cq = lane & 3;
    int aoff = (wm * 64 + g) * LDA + cq;
    int boff = (wn * 32 + g) * LDA + cq;

    const int NIT = DIM / BK;   // 8
    for (int it = 0; it < NIT; it++) {
        int cur = it & 1;
        bool more = (it + 1 < NIT);
        if (more) ISSUE(cur ^ 1, (it + 1) * BK)

        if (more) asm volatile("cp.async.wait_group 1;" ::: "memory");
        else      asm volatile("cp.async.wait_group 0;" ::: "memory");
        __syncthreads();

        const float* Ac = sm + (cur ? OFF_A1 : OFF_A0);
        const float* Bc = sm + (cur ? OFF_B1 : OFF_B0);
        #pragma unroll
        for (int ks = 0; ks < 4; ks++) {
            int kc = ks * 8;
            uint32_t bf[4][2];
            #pragma unroll
            for (int nt = 0; nt < 4; nt++) {
                bf[nt][0] = __float_as_uint(Bc[boff + nt * 8 * LDA + kc]);
                bf[nt][1] = __float_as_uint(Bc[boff + nt * 8 * LDA + kc + 4]);
            }
            #pragma unroll
            for (int mt = 0; mt < 4; mt++) {
                uint32_t a0 = __float_as_uint(Ac[aoff + (mt * 16)     * LDA + kc]);
                uint32_t a1 = __float_as_uint(Ac[aoff + (mt * 16 + 8) * LDA + kc]);
                uint32_t a2 = __float_as_uint(Ac[aoff + (mt * 16)     * LDA + kc + 4]);
                uint32_t a3 = __float_as_uint(Ac[aoff + (mt * 16 + 8) * LDA + kc + 4]);
                #pragma unroll
                for (int nt = 0; nt < 4; nt++)
                    mma_tf32(acc[mt * 4 + nt], a0, a1, a2, a3, bf[nt][0], bf[nt][1]);
            }
        }
        __syncthreads();
    }

    // Epilogue on register fragments.
    float c = g_coef;
    float twoC = 2.f * c;
    float rA[8], cB[8];
    #pragma unroll
    for (int mt = 0; mt < 4; mt++) {
        rA[mt * 2 + 0] = sA[wm * 64 + mt * 16 + g]     * c;
        rA[mt * 2 + 1] = sA[wm * 64 + mt * 16 + g + 8] * c;
    }
    #pragma unroll
    for (int nt = 0; nt < 4; nt++) {
        cB[nt * 2 + 0] = sBn[wn * 32 + nt * 8 + cq * 2]     * c;
        cB[nt * 2 + 1] = sBn[wn * 32 + nt * 8 + cq * 2 + 1] * c;
    }

    float psum = 0.f;
    #pragma unroll
    for (int mt = 0; mt < 4; mt++) {
        #pragma unroll
        for (int nt = 0; nt < 4; nt++) {
            float* cc = acc[mt * 4 + nt];
            #pragma unroll
            for (int u = 0; u < 4; u++) {
                int h = u >> 1, e = u & 1;
                float arg = fmaf(cc[u], twoC, -(rA[mt * 2 + h] + cB[nt * 2 + e]));
                arg = fminf(arg, 0.f);           // d2 clamp
                float ee = ex2f(arg);            // mult 4
                float t2 = ee * ee;              // mult 2
                float ks = ee + t2;
                float t4 = t2 * t2;  ks += t4;   // mult 1
                float t8 = t4 * t4;  ks += t8;   // mult 1/2
                ks = fmaf(t8, t8, ks);           // mult 1/4
                psum += ks;
            }
        }
    }

    double wsum = (double)psum;
    #pragma unroll
    for (int o = 16; o; o >>= 1) wsum += __shfl_xor_sync(0xffffffffu, wsum, o);
    if (lane == 0) red[wid] = wsum;
    __syncthreads();
    if (tid == 0) {
        double s = 0.0;
        #pragma unroll
        for (int w = 0; w < 8; w++) s += red[w];
        double wgt = ((ti < HALF_TILES) == (tj < HALF_TILES)) ? 1.0 : -1.0;
        if (ti != tj) wgt *= 2.0;
        g_part[L] = s * wgt;
    }
}

// ---------------------------------------------------------------------------
// Final deterministic reduction + scale.
// ---------------------------------------------------------------------------
__global__ void __launch_bounds__(256) k_final(float* __restrict__ out) {
    __shared__ double sh[256];
    int t = threadIdx.x;
    double a = 0.0;
    for (int i = t; i < NPAIRS; i += 256) a += g_part[i];
    sh[t] = a; __syncthreads();
    for (int o = 128; o; o >>= 1) { if (t < o) sh[t] += sh[t + o]; __syncthreads(); }
    if (t == 0)
        out[0] = (float)(sh[0] / ((double)N_HALF * (double)N_HALF));
}

extern "C" void kernel_launch(void* const* d_in, const int* in_sizes, int n_in,
                              void* d_out, int out_size) {
    const float* X = (const float*)d_in[0];
    const float* Y = (const float*)d_in[1];
    float* out = (float*)d_out;
    (void)in_sizes; (void)n_in; (void)out_size;

    cudaFuncSetAttribute(k_main, cudaFuncAttributeMaxDynamicSharedMemorySize, SMEM_BYTES);

    k_pre<<<256, 256>>>(X, Y);
    k_bw<<<1, 256>>>();
    k_main<<<NPAIRS, 256, SMEM_BYTES>>>();
    k_final<<<1, 256>>>(out);
}